// round 3
// baseline (speedup 1.0000x reference)
#include <cuda_runtime.h>
#include <cuda_bf16.h>
#include <stdint.h>

// Problem constants
#define B_   128
#define L_   100
#define F_   900     // C * CURVE = 3 * 300
#define D_   512
#define E_   8

// Tiling
#define BM   128     // L tile (padded from 100)
#define BN   128     // D tile
#define BK   32      // F tile
#define SSTR 132     // smem row stride (pad to break bank conflicts, keep 16B align)

// Gating results (device-global scratch; no allocation allowed)
__device__ int2   g_topk_idx[B_];
__device__ float2 g_topk_w[B_];

// ---------------------------------------------------------------------------
// Kernel 1: masked softmax -> top-2 -> renormalize.  One thread per sample.
// Disambiguates logits (random fp32) from moe_masks (int32 in {0,1}) by bit
// pattern, so argument order doesn't matter.
// ---------------------------------------------------------------------------
__global__ void gates_kernel(const void* __restrict__ candA,
                             const void* __restrict__ candB) {
    int b = threadIdx.x;
    if (b >= B_) return;

    const int* ai = (const int*)candA;
    bool aIsMask = true;
#pragma unroll
    for (int e = 0; e < E_; e++) {
        int t = ai[b * E_ + e];
        if (t != 0 && t != 1) aIsMask = false;
    }
    const float* logits = aIsMask ? (const float*)candB : (const float*)candA;
    const int*   masks  = aIsMask ? (const int*)candA   : (const int*)candB;

    float v[E_];
    float mx = -1e30f;
#pragma unroll
    for (int e = 0; e < E_; e++) {
        v[e] = logits[b * E_ + e];
        mx = fmaxf(mx, v[e]);
    }
    float s = 0.f;
#pragma unroll
    for (int e = 0; e < E_; e++) {
        v[e] = expf(v[e] - mx);
        s += v[e];
    }
    float inv = 1.f / s;
#pragma unroll
    for (int e = 0; e < E_; e++) {
        float m = (masks[b * E_ + e] == 1) ? 1.f : 0.f;
        v[e] = v[e] * inv * m;
    }
    // top-2, ties -> lower index (matches jax.lax.top_k)
    int i1 = 0;
#pragma unroll
    for (int e = 1; e < E_; e++) if (v[e] > v[i1]) i1 = e;
    int i2 = (i1 == 0) ? 1 : 0;
#pragma unroll
    for (int e = 0; e < E_; e++) if (e != i1 && v[e] > v[i2]) i2 = e;

    float g1 = v[i1], g2 = v[i2];
    float invs = 1.f / (g1 + g2 + 1e-9f);
    g_topk_idx[b] = make_int2(i1, i2);
    g_topk_w[b]   = make_float2(g1 * invs, g2 * invs);
}

// ---------------------------------------------------------------------------
// Kernel 2: per-sample GEMM with on-the-fly gate-mixed expert weights.
//   out[b, l, d] = sum_f x[b,l,f] * (g1*W[e1,d,f] + g2*W[e2,d,f]) + bmix[d]
// Block: one (b, 128-wide D tile).  256 threads, 8x8 per-thread micro-tile.
// Output: FLOAT32 buffer, values rounded through bf16 to match the reference.
// ---------------------------------------------------------------------------
__global__ void __launch_bounds__(256, 2)
moe_gemm_kernel(const float* __restrict__ x,
                const float* __restrict__ W,
                const float* __restrict__ bias,
                float* __restrict__ out) {
    __shared__ float As[BK][SSTR];   // [k][l]
    __shared__ float Bs[BK][SSTR];   // [k][d]

    const int b     = blockIdx.y;
    const int dtile = blockIdx.x;            // 0..3
    const int tid   = threadIdx.x;           // 0..255
    const int ty    = tid >> 4;              // 0..15 (L dim)
    const int tx    = tid & 15;              // 0..15 (D dim)

    const int2   ei = g_topk_idx[b];
    const float2 gw = g_topk_w[b];

    const float* __restrict__ xb = x + (size_t)b * L_ * F_;
    const float* __restrict__ W1 = W + (size_t)ei.x * D_ * F_ + (size_t)dtile * BN * F_;
    const float* __restrict__ W2 = W + (size_t)ei.y * D_ * F_ + (size_t)dtile * BN * F_;

    float acc[8][8];
#pragma unroll
    for (int i = 0; i < 8; i++)
#pragma unroll
        for (int j = 0; j < 8; j++) acc[i][j] = 0.f;

    // 29 K-tiles: 928 = 29*32 (F=900 zero-padded)
    for (int k0 = 0; k0 < 928; k0 += BK) {
        // ---- load & transpose A (x tile): 128 rows x 32 f ----
#pragma unroll
        for (int v = 0; v < 4; v++) {
            int idx = tid + v * 256;
            int row = idx >> 3;          // 0..127 (l)
            int c4  = idx & 7;           // float4 column
            int f   = k0 + c4 * 4;
            float4 val = make_float4(0.f, 0.f, 0.f, 0.f);
            if (row < L_ && f < F_)
                val = *(const float4*)(xb + (size_t)row * F_ + f);
            int k = c4 * 4;
            As[k + 0][row] = val.x;
            As[k + 1][row] = val.y;
            As[k + 2][row] = val.z;
            As[k + 3][row] = val.w;
        }
        // ---- load, gate-mix & transpose B (weight tile): 128 d x 32 f ----
#pragma unroll
        for (int v = 0; v < 4; v++) {
            int idx = tid + v * 256;
            int row = idx >> 3;          // 0..127 (d within tile)
            int c4  = idx & 7;
            int f   = k0 + c4 * 4;
            float4 wv = make_float4(0.f, 0.f, 0.f, 0.f);
            if (f < F_) {
                float4 w1 = *(const float4*)(W1 + (size_t)row * F_ + f);
                float4 w2 = *(const float4*)(W2 + (size_t)row * F_ + f);
                wv.x = gw.x * w1.x + gw.y * w2.x;
                wv.y = gw.x * w1.y + gw.y * w2.y;
                wv.z = gw.x * w1.z + gw.y * w2.z;
                wv.w = gw.x * w1.w + gw.y * w2.w;
            }
            int k = c4 * 4;
            Bs[k + 0][row] = wv.x;
            Bs[k + 1][row] = wv.y;
            Bs[k + 2][row] = wv.z;
            Bs[k + 3][row] = wv.w;
        }
        __syncthreads();

        // ---- FMA mainloop ----
#pragma unroll
        for (int k = 0; k < BK; k++) {
            float4 a0 = *(const float4*)&As[k][ty * 8];
            float4 a1 = *(const float4*)&As[k][ty * 8 + 4];
            float4 b0 = *(const float4*)&Bs[k][tx * 8];
            float4 b1 = *(const float4*)&Bs[k][tx * 8 + 4];
            float av[8] = {a0.x, a0.y, a0.z, a0.w, a1.x, a1.y, a1.z, a1.w};
            float bv[8] = {b0.x, b0.y, b0.z, b0.w, b1.x, b1.y, b1.z, b1.w};
#pragma unroll
            for (int i = 0; i < 8; i++)
#pragma unroll
                for (int j = 0; j < 8; j++)
                    acc[i][j] = fmaf(av[i], bv[j], acc[i][j]);
        }
        __syncthreads();
    }

    // ---- epilogue: add mixed bias, round through bf16, store as FP32 ----
    const int d0 = dtile * BN + tx * 8;
    float bm[8];
#pragma unroll
    for (int j = 0; j < 8; j++)
        bm[j] = gw.x * bias[ei.x * D_ + d0 + j] + gw.y * bias[ei.y * D_ + d0 + j];

#pragma unroll
    for (int i = 0; i < 8; i++) {
        int l = ty * 8 + i;
        if (l < L_) {
            float o[8];
#pragma unroll
            for (int j = 0; j < 8; j++)
                o[j] = __bfloat162float(__float2bfloat16(acc[i][j] + bm[j]));
            float* dst = out + ((size_t)b * L_ + l) * D_ + d0;
            *(float4*)(dst)     = make_float4(o[0], o[1], o[2], o[3]);
            *(float4*)(dst + 4) = make_float4(o[4], o[5], o[6], o[7]);
        }
    }
}

// ---------------------------------------------------------------------------
// Resolve inputs by element count (robust to metadata ordering):
//   x = 11,520,000   W = 3,686,400   b = 4,096   logits / masks = 1,024 each
// ---------------------------------------------------------------------------
extern "C" void kernel_launch(void* const* d_in, const int* in_sizes, int n_in,
                              void* d_out, int out_size) {
    const void* x_p = nullptr;
    const void* W_p = nullptr;
    const void* b_p = nullptr;
    const void* c1024[2] = {nullptr, nullptr};
    int n1024 = 0;

    for (int i = 0; i < n_in; i++) {
        switch (in_sizes[i]) {
            case 11520000: x_p = d_in[i]; break;
            case 3686400:  W_p = d_in[i]; break;
            case 4096:     b_p = d_in[i]; break;
            case 1024:
                if (n1024 < 2) c1024[n1024++] = d_in[i];
                break;
            default: break;
        }
    }
    // Fallback to positional (setup_inputs dict) order if size matching failed
    if (!x_p || !W_p || !b_p || n1024 != 2) {
        x_p = d_in[0]; c1024[0] = d_in[1]; c1024[1] = d_in[2];
        W_p = d_in[3]; b_p = d_in[4];
    }

    float* out = (float*)d_out;   // [B, L, D] stored as fp32 (bf16-rounded values)

    gates_kernel<<<1, B_>>>(c1024[0], c1024[1]);

    dim3 grid(D_ / BN, B_);   // (4, 128)
    moe_gemm_kernel<<<grid, 256>>>((const float*)x_p, (const float*)W_p,
                                   (const float*)b_p, out);
}

// round 5
// speedup vs baseline: 1.4356x; 1.4356x over previous
#include <cuda_runtime.h>
#include <cuda_bf16.h>
#include <stdint.h>

// Problem constants
#define B_   128
#define L_   100
#define F_   900     // C * CURVE
#define D_   512
#define E_   8

#define BN   128     // D tile per block
#define BK   64      // f tile (64 bf16 = 128 B/row -> SW128-style swizzle)
#define NKT  15      // ceil(900/64), F padded to 960

// Shared memory layout (dynamic)
#define SM_BM     0        // 128 floats mixed bias
#define SM_STAGES 1024
#define STAGE_BYTES 65536
#define OFF_A_HI  0
#define OFF_A_LO  16384
#define OFF_B_HI  32768
#define OFF_B_LO  49152
#define SMEM_TOTAL (SM_STAGES + 2 * STAGE_BYTES)   // 132096

// Gating results
__device__ int2   g_topk_idx[B_];
__device__ float2 g_topk_w[B_];

// ---------------- helpers ----------------
__device__ __forceinline__ uint32_t smem_u32(const void* p) {
    uint32_t a;
    asm("{ .reg .u64 t; cvta.to.shared.u64 t, %1; cvt.u32.u64 %0, t; }" : "=r"(a) : "l"(p));
    return a;
}

#define LDSM4(r, addr) \
    asm volatile("ldmatrix.sync.aligned.m8n8.x4.shared.b16 {%0,%1,%2,%3}, [%4];" \
        : "=r"((r)[0]), "=r"((r)[1]), "=r"((r)[2]), "=r"((r)[3]) : "r"(addr))
#define LDSM2(r, addr) \
    asm volatile("ldmatrix.sync.aligned.m8n8.x2.shared.b16 {%0,%1}, [%2];" \
        : "=r"((r)[0]), "=r"((r)[1]) : "r"(addr))
#define MMA16816(c, a, bb) \
    asm volatile("mma.sync.aligned.m16n8k16.row.col.f32.bf16.bf16.f32 " \
        "{%0,%1,%2,%3}, {%4,%5,%6,%7}, {%8,%9}, {%0,%1,%2,%3};" \
        : "+f"((c)[0]), "+f"((c)[1]), "+f"((c)[2]), "+f"((c)[3]) \
        : "r"((a)[0]), "r"((a)[1]), "r"((a)[2]), "r"((a)[3]), "r"((bb)[0]), "r"((bb)[1]))

// ---------------------------------------------------------------------------
// Kernel 1: gates (self-disambiguates logits vs masks by bit pattern)
// ---------------------------------------------------------------------------
__global__ void gates_kernel(const void* __restrict__ candA,
                             const void* __restrict__ candB) {
    int b = threadIdx.x;
    if (b >= B_) return;
    const int* ai = (const int*)candA;
    bool aIsMask = true;
#pragma unroll
    for (int e = 0; e < E_; e++) {
        int t = ai[b * E_ + e];
        if (t != 0 && t != 1) aIsMask = false;
    }
    const float* logits = aIsMask ? (const float*)candB : (const float*)candA;
    const int*   masks  = aIsMask ? (const int*)candA   : (const int*)candB;

    float v[E_]; float mx = -1e30f;
#pragma unroll
    for (int e = 0; e < E_; e++) { v[e] = logits[b * E_ + e]; mx = fmaxf(mx, v[e]); }
    float s = 0.f;
#pragma unroll
    for (int e = 0; e < E_; e++) { v[e] = expf(v[e] - mx); s += v[e]; }
    float inv = 1.f / s;
#pragma unroll
    for (int e = 0; e < E_; e++) {
        float m = (masks[b * E_ + e] == 1) ? 1.f : 0.f;
        v[e] = v[e] * inv * m;
    }
    int i1 = 0;
#pragma unroll
    for (int e = 1; e < E_; e++) if (v[e] > v[i1]) i1 = e;
    int i2 = (i1 == 0) ? 1 : 0;
#pragma unroll
    for (int e = 0; e < E_; e++) if (e != i1 && v[e] > v[i2]) i2 = e;
    float g1 = v[i1], g2 = v[i2];
    float invs = 1.f / (g1 + g2 + 1e-9f);
    g_topk_idx[b] = make_int2(i1, i2);
    g_topk_w[b]   = make_float2(g1 * invs, g2 * invs);
}

// ---------------------------------------------------------------------------
// Producer: fp32 -> bf16 hi/lo split tiles into swizzled smem.
// Work item = (row 0..127, 16B chunk 0..7); 1024 items in 4 sweeps of 256 thr.
// swizzle: chunk' = chunk ^ (row & 7)   (128 B rows -> SW128 pattern)
// ---------------------------------------------------------------------------
__device__ __forceinline__ void split8_store(char* hi_p, char* lo_p, const float* v) {
    uint32_t hi[4], lo[4];
#pragma unroll
    for (int j = 0; j < 4; j++) {
        __nv_bfloat16 h0 = __float2bfloat16_rn(v[2 * j]);
        __nv_bfloat16 h1 = __float2bfloat16_rn(v[2 * j + 1]);
        float l0f = v[2 * j]     - __bfloat162float(h0);
        float l1f = v[2 * j + 1] - __bfloat162float(h1);
        __nv_bfloat162 hp; hp.x = h0; hp.y = h1;
        __nv_bfloat162 lp; lp.x = __float2bfloat16_rn(l0f); lp.y = __float2bfloat16_rn(l1f);
        hi[j] = *(uint32_t*)&hp;
        lo[j] = *(uint32_t*)&lp;
    }
    *(uint4*)hi_p = make_uint4(hi[0], hi[1], hi[2], hi[3]);
    *(uint4*)lo_p = make_uint4(lo[0], lo[1], lo[2], lo[3]);
}

__device__ __forceinline__ void produce_tile(
    char* __restrict__ stg,
    const float* __restrict__ xb,
    const float* __restrict__ W1,
    const float* __restrict__ W2,
    float gx, float gy, int k0, int tid) {
    // ---- A: x[128 l x 64 f] ----
#pragma unroll
    for (int it = 0; it < 4; it++) {
        int idx = tid + it * 256;
        int row = idx >> 3;
        int ch  = idx & 7;
        int f   = k0 + ch * 8;
        float v[8] = {0.f, 0.f, 0.f, 0.f, 0.f, 0.f, 0.f, 0.f};
        if (row < L_) {
            if (f < F_)     *(float4*)&v[0] = *(const float4*)(xb + (size_t)row * F_ + f);
            if (f + 4 < F_) *(float4*)&v[4] = *(const float4*)(xb + (size_t)row * F_ + f + 4);
        }
        uint32_t off = (uint32_t)(row * 128) + (uint32_t)((ch ^ (row & 7)) << 4);
        split8_store(stg + OFF_A_HI + off, stg + OFF_A_LO + off, v);
    }
    // ---- B: gate-mixed W[128 d x 64 f] ----
#pragma unroll
    for (int it = 0; it < 4; it++) {
        int idx = tid + it * 256;
        int row = idx >> 3;
        int ch  = idx & 7;
        int f   = k0 + ch * 8;
        float v[8] = {0.f, 0.f, 0.f, 0.f, 0.f, 0.f, 0.f, 0.f};
        if (f < F_) {
            float4 a = *(const float4*)(W1 + (size_t)row * F_ + f);
            float4 c = *(const float4*)(W2 + (size_t)row * F_ + f);
            v[0] = fmaf(gx, a.x, gy * c.x); v[1] = fmaf(gx, a.y, gy * c.y);
            v[2] = fmaf(gx, a.z, gy * c.z); v[3] = fmaf(gx, a.w, gy * c.w);
        }
        if (f + 4 < F_) {
            float4 a = *(const float4*)(W1 + (size_t)row * F_ + f + 4);
            float4 c = *(const float4*)(W2 + (size_t)row * F_ + f + 4);
            v[4] = fmaf(gx, a.x, gy * c.x); v[5] = fmaf(gx, a.y, gy * c.y);
            v[6] = fmaf(gx, a.z, gy * c.z); v[7] = fmaf(gx, a.w, gy * c.w);
        }
        uint32_t off = (uint32_t)(row * 128) + (uint32_t)((ch ^ (row & 7)) << 4);
        split8_store(stg + OFF_B_HI + off, stg + OFF_B_LO + off, v);
    }
}

// ---------------------------------------------------------------------------
// Kernel 2: HMMA (mma.sync bf16, 3-pass split) gate-mixed GEMM.
//   One block = (sample b) x (128-wide D tile).  8 warps = 2(M) x 4(N).
// ---------------------------------------------------------------------------
__global__ void __launch_bounds__(256, 1)
moe_hmma_kernel(const float* __restrict__ x,
                const float* __restrict__ W,
                const float* __restrict__ bias,
                float* __restrict__ out) {
    extern __shared__ char smem[];
    float* bm = (float*)(smem + SM_BM);

    const int tid    = threadIdx.x;
    const int wid    = tid >> 5;
    const int lane   = tid & 31;
    const int warp_m = wid >> 2;           // 0..1
    const int warp_n = wid & 3;            // 0..3
    const int b      = blockIdx.y;
    const int dtile  = blockIdx.x;

    const int2   ei = g_topk_idx[b];
    const float2 gw = g_topk_w[b];

    const float* __restrict__ xb = x + (size_t)b * L_ * F_;
    const float* __restrict__ W1 = W + (size_t)ei.x * D_ * F_ + (size_t)dtile * BN * F_;
    const float* __restrict__ W2 = W + (size_t)ei.y * D_ * F_ + (size_t)dtile * BN * F_;

    // mixed bias
    if (tid < BN) {
        int d = dtile * BN + tid;
        bm[tid] = gw.x * bias[ei.x * D_ + d] + gw.y * bias[ei.y * D_ + d];
    }

    float acc[4][4][4];
#pragma unroll
    for (int mi = 0; mi < 4; mi++)
#pragma unroll
        for (int nj = 0; nj < 4; nj++)
#pragma unroll
            for (int q = 0; q < 4; q++) acc[mi][nj][q] = 0.f;

    produce_tile(smem + SM_STAGES, xb, W1, W2, gw.x, gw.y, 0, tid);
    __syncthreads();

    for (int t = 0; t < NKT; t++) {
        char* cbuf = smem + SM_STAGES + (t & 1) * STAGE_BYTES;
        const uint32_t aHiB = smem_u32(cbuf + OFF_A_HI);
        const uint32_t aLoB = smem_u32(cbuf + OFF_A_LO);
        const uint32_t bHiB = smem_u32(cbuf + OFF_B_HI);
        const uint32_t bLoB = smem_u32(cbuf + OFF_B_LO);

        const int arow  = warp_m * 64 + (lane & 15);
        const int ahalf = lane >> 4;
        const int brow  = warp_n * 32 + (lane & 7);
        const int bhalf = (lane >> 3) & 1;

#pragma unroll
        for (int s = 0; s < 4; s++) {      // 4 k16 steps per 64-wide tile
            uint32_t aH[4][4], aL[4][4], bH[4][2], bL[4][2];
#pragma unroll
            for (int mi = 0; mi < 4; mi++) {
                int row = arow + mi * 16;
                int ch  = (s << 1) + ahalf;
                uint32_t off = (uint32_t)(row * 128) + (uint32_t)((ch ^ (row & 7)) << 4);
                LDSM4(aH[mi], aHiB + off);
                LDSM4(aL[mi], aLoB + off);
            }
#pragma unroll
            for (int nj = 0; nj < 4; nj++) {
                int row = brow + nj * 8;
                int ch  = (s << 1) + bhalf;
                uint32_t off = (uint32_t)(row * 128) + (uint32_t)((ch ^ (row & 7)) << 4);
                LDSM2(bH[nj], bHiB + off);
                LDSM2(bL[nj], bLoB + off);
            }
#pragma unroll
            for (int mi = 0; mi < 4; mi++)
#pragma unroll
                for (int nj = 0; nj < 4; nj++) {
                    MMA16816(acc[mi][nj], aH[mi], bH[nj]);
                    MMA16816(acc[mi][nj], aH[mi], bL[nj]);
                    MMA16816(acc[mi][nj], aL[mi], bH[nj]);
                }
        }

        if (t + 1 < NKT)
            produce_tile(smem + SM_STAGES + ((t + 1) & 1) * STAGE_BYTES,
                         xb, W1, W2, gw.x, gw.y, (t + 1) * BK, tid);
        __syncthreads();
    }

    // ---- epilogue: bias add, bf16 rounding, direct fp32 store ----
    const int r_base = warp_m * 64 + (lane >> 2);
    const int c_base = warp_n * 32 + ((lane & 3) << 1);
#pragma unroll
    for (int mi = 0; mi < 4; mi++) {
#pragma unroll
        for (int half = 0; half < 2; half++) {
            int l = r_base + mi * 16 + half * 8;
            if (l >= L_) continue;
            float* orow = out + ((size_t)b * L_ + l) * D_ + dtile * BN;
#pragma unroll
            for (int nj = 0; nj < 4; nj++) {
                int c = c_base + nj * 8;
                float v0 = acc[mi][nj][half * 2 + 0] + bm[c];
                float v1 = acc[mi][nj][half * 2 + 1] + bm[c + 1];
                v0 = __bfloat162float(__float2bfloat16_rn(v0));
                v1 = __bfloat162float(__float2bfloat16_rn(v1));
                *(float2*)(orow + c) = make_float2(v0, v1);
            }
        }
    }
}

// ---------------------------------------------------------------------------
extern "C" void kernel_launch(void* const* d_in, const int* in_sizes, int n_in,
                              void* d_out, int out_size) {
    const void* x_p = nullptr;
    const void* W_p = nullptr;
    const void* b_p = nullptr;
    const void* c1024[2] = {nullptr, nullptr};
    int n1024 = 0;

    for (int i = 0; i < n_in; i++) {
        switch (in_sizes[i]) {
            case 11520000: x_p = d_in[i]; break;
            case 3686400:  W_p = d_in[i]; break;
            case 4096:     b_p = d_in[i]; break;
            case 1024: if (n1024 < 2) c1024[n1024++] = d_in[i]; break;
            default: break;
        }
    }
    if (!x_p || !W_p || !b_p || n1024 != 2) {
        x_p = d_in[0]; c1024[0] = d_in[1]; c1024[1] = d_in[2];
        W_p = d_in[3]; b_p = d_in[4];
    }

    float* out = (float*)d_out;

    cudaFuncSetAttribute(moe_hmma_kernel,
                         cudaFuncAttributeMaxDynamicSharedMemorySize, SMEM_TOTAL);

    gates_kernel<<<1, B_>>>(c1024[0], c1024[1]);

    dim3 grid(D_ / BN, B_);   // (4, 128)
    moe_hmma_kernel<<<grid, 256, SMEM_TOTAL>>>((const float*)x_p, (const float*)W_p,
                                               (const float*)b_p, out);
}

// round 6
// speedup vs baseline: 2.1842x; 1.5215x over previous
#include <cuda_runtime.h>
#include <cuda_bf16.h>
#include <stdint.h>

// Problem constants
#define B_   128
#define L_   100
#define F_   900     // C * CURVE
#define D_   512
#define E_   8

#define BN   128     // D tile per block
#define BK   32      // f tile (32 bf16 = 64 B/row)
#define NKT  29      // ceil(900/32), F padded to 928

// Shared memory layout (dynamic)
#define SM_BM     0        // 128 floats mixed bias
#define SM_STAGES 1024
#define STAGE_BYTES 32768
#define OFF_A_HI  0
#define OFF_A_LO  8192
#define OFF_B_HI  16384
#define OFF_B_LO  24576
#define SMEM_TOTAL (SM_STAGES + 2 * STAGE_BYTES)   // 66560 -> 2 CTAs/SM

// Gating results
__device__ int2   g_topk_idx[B_];
__device__ float2 g_topk_w[B_];

// ---------------- helpers ----------------
__device__ __forceinline__ uint32_t smem_u32(const void* p) {
    uint32_t a;
    asm("{ .reg .u64 t; cvta.to.shared.u64 t, %1; cvt.u32.u64 %0, t; }" : "=r"(a) : "l"(p));
    return a;
}
// 64 B rows: quarter q in 0..3, phys quarter = q ^ ((row>>1)&3).
// (row&1, physq) is injective over 8 consecutive rows -> ldmatrix conflict-free.
__device__ __forceinline__ uint32_t swoff(int row, int q) {
    return (uint32_t)(row * 64) + (uint32_t)((q ^ ((row >> 1) & 3)) << 4);
}

#define LDSM4(r, addr) \
    asm volatile("ldmatrix.sync.aligned.m8n8.x4.shared.b16 {%0,%1,%2,%3}, [%4];" \
        : "=r"((r)[0]), "=r"((r)[1]), "=r"((r)[2]), "=r"((r)[3]) : "r"(addr))
#define LDSM2(r, addr) \
    asm volatile("ldmatrix.sync.aligned.m8n8.x2.shared.b16 {%0,%1}, [%2];" \
        : "=r"((r)[0]), "=r"((r)[1]) : "r"(addr))
#define MMA16816(c, a, bb) \
    asm volatile("mma.sync.aligned.m16n8k16.row.col.f32.bf16.bf16.f32 " \
        "{%0,%1,%2,%3}, {%4,%5,%6,%7}, {%8,%9}, {%0,%1,%2,%3};" \
        : "+f"((c)[0]), "+f"((c)[1]), "+f"((c)[2]), "+f"((c)[3]) \
        : "r"((a)[0]), "r"((a)[1]), "r"((a)[2]), "r"((a)[3]), "r"((bb)[0]), "r"((bb)[1]))

// ---------------------------------------------------------------------------
// Kernel 1: gates (self-disambiguates logits vs masks by bit pattern)
// ---------------------------------------------------------------------------
__global__ void gates_kernel(const void* __restrict__ candA,
                             const void* __restrict__ candB) {
    int b = threadIdx.x;
    if (b >= B_) return;
    const int* ai = (const int*)candA;
    bool aIsMask = true;
#pragma unroll
    for (int e = 0; e < E_; e++) {
        int t = ai[b * E_ + e];
        if (t != 0 && t != 1) aIsMask = false;
    }
    const float* logits = aIsMask ? (const float*)candB : (const float*)candA;
    const int*   masks  = aIsMask ? (const int*)candA   : (const int*)candB;

    float v[E_]; float mx = -1e30f;
#pragma unroll
    for (int e = 0; e < E_; e++) { v[e] = logits[b * E_ + e]; mx = fmaxf(mx, v[e]); }
    float s = 0.f;
#pragma unroll
    for (int e = 0; e < E_; e++) { v[e] = expf(v[e] - mx); s += v[e]; }
    float inv = 1.f / s;
#pragma unroll
    for (int e = 0; e < E_; e++) {
        float m = (masks[b * E_ + e] == 1) ? 1.f : 0.f;
        v[e] = v[e] * inv * m;
    }
    int i1 = 0;
#pragma unroll
    for (int e = 1; e < E_; e++) if (v[e] > v[i1]) i1 = e;
    int i2 = (i1 == 0) ? 1 : 0;
#pragma unroll
    for (int e = 0; e < E_; e++) if (e != i1 && v[e] > v[i2]) i2 = e;
    float g1 = v[i1], g2 = v[i2];
    float invs = 1.f / (g1 + g2 + 1e-9f);
    g_topk_idx[b] = make_int2(i1, i2);
    g_topk_w[b]   = make_float2(g1 * invs, g2 * invs);
}

// ---------------------------------------------------------------------------
// Producer: one item = (row, 16B quarter) = 8 fp32 -> 8 bf16 hi + 8 bf16 lo.
// ---------------------------------------------------------------------------
__device__ __forceinline__ void split8_store(char* hi_p, char* lo_p, const float* v) {
    uint32_t hi[4], lo[4];
#pragma unroll
    for (int j = 0; j < 4; j++) {
        __nv_bfloat16 h0 = __float2bfloat16_rn(v[2 * j]);
        __nv_bfloat16 h1 = __float2bfloat16_rn(v[2 * j + 1]);
        float l0f = v[2 * j]     - __bfloat162float(h0);
        float l1f = v[2 * j + 1] - __bfloat162float(h1);
        __nv_bfloat162 hp; hp.x = h0; hp.y = h1;
        __nv_bfloat162 lp; lp.x = __float2bfloat16_rn(l0f); lp.y = __float2bfloat16_rn(l1f);
        hi[j] = *(uint32_t*)&hp;
        lo[j] = *(uint32_t*)&lp;
    }
    *(uint4*)hi_p = make_uint4(hi[0], hi[1], hi[2], hi[3]);
    *(uint4*)lo_p = make_uint4(lo[0], lo[1], lo[2], lo[3]);
}

__device__ __forceinline__ void produce_tile(
    char* __restrict__ stg,
    const float* __restrict__ xb,
    const float* __restrict__ W1,
    const float* __restrict__ W2,
    float gx, float gy, int k0, int tid) {
    // ---- A: x[128 l x 32 f]: 512 quarter-items, 2 sweeps ----
#pragma unroll
    for (int it = 0; it < 2; it++) {
        int item = tid + it * 256;
        int row  = item >> 2;
        int q    = item & 3;
        int f    = k0 + q * 8;
        float v[8] = {0.f, 0.f, 0.f, 0.f, 0.f, 0.f, 0.f, 0.f};
        if (row < L_) {
            if (f + 4 <= F_) *(float4*)&v[0] = *(const float4*)(xb + (size_t)row * F_ + f);
            if (f + 8 <= F_) *(float4*)&v[4] = *(const float4*)(xb + (size_t)row * F_ + f + 4);
        }
        uint32_t off = swoff(row, q);
        split8_store(stg + OFF_A_HI + off, stg + OFF_A_LO + off, v);
    }
    // ---- B: gate-mixed W[128 d x 32 f] ----
#pragma unroll
    for (int it = 0; it < 2; it++) {
        int item = tid + it * 256;
        int row  = item >> 2;
        int q    = item & 3;
        int f    = k0 + q * 8;
        float v[8] = {0.f, 0.f, 0.f, 0.f, 0.f, 0.f, 0.f, 0.f};
        if (f + 4 <= F_) {
            float4 a = *(const float4*)(W1 + (size_t)row * F_ + f);
            float4 c = *(const float4*)(W2 + (size_t)row * F_ + f);
            v[0] = fmaf(gx, a.x, gy * c.x); v[1] = fmaf(gx, a.y, gy * c.y);
            v[2] = fmaf(gx, a.z, gy * c.z); v[3] = fmaf(gx, a.w, gy * c.w);
        }
        if (f + 8 <= F_) {
            float4 a = *(const float4*)(W1 + (size_t)row * F_ + f + 4);
            float4 c = *(const float4*)(W2 + (size_t)row * F_ + f + 4);
            v[4] = fmaf(gx, a.x, gy * c.x); v[5] = fmaf(gx, a.y, gy * c.y);
            v[6] = fmaf(gx, a.z, gy * c.z); v[7] = fmaf(gx, a.w, gy * c.w);
        }
        uint32_t off = swoff(row, q);
        split8_store(stg + OFF_B_HI + off, stg + OFF_B_LO + off, v);
    }
}

// ---------------------------------------------------------------------------
// Kernel 2: HMMA bf16 3-pass split GEMM, 2 CTAs/SM (regs<=128, smem 65KB).
//   8 warps = 2(M) x 4(N); warp tile 64x32.
// ---------------------------------------------------------------------------
__global__ void __launch_bounds__(256, 2)
moe_hmma_kernel(const float* __restrict__ x,
                const float* __restrict__ W,
                const float* __restrict__ bias,
                float* __restrict__ out) {
    extern __shared__ char smem[];
    float* bm = (float*)(smem + SM_BM);

    const int tid    = threadIdx.x;
    const int wid    = tid >> 5;
    const int lane   = tid & 31;
    const int warp_m = wid >> 2;           // 0..1
    const int warp_n = wid & 3;            // 0..3
    const int b      = blockIdx.y;
    const int dtile  = blockIdx.x;

    const int2   ei = g_topk_idx[b];
    const float2 gw = g_topk_w[b];

    const float* __restrict__ xb = x + (size_t)b * L_ * F_;
    const float* __restrict__ W1 = W + (size_t)ei.x * D_ * F_ + (size_t)dtile * BN * F_;
    const float* __restrict__ W2 = W + (size_t)ei.y * D_ * F_ + (size_t)dtile * BN * F_;

    if (tid < BN) {
        int d = dtile * BN + tid;
        bm[tid] = gw.x * bias[ei.x * D_ + d] + gw.y * bias[ei.y * D_ + d];
    }

    float acc[4][4][4];
#pragma unroll
    for (int mi = 0; mi < 4; mi++)
#pragma unroll
        for (int nj = 0; nj < 4; nj++)
#pragma unroll
            for (int q = 0; q < 4; q++) acc[mi][nj][q] = 0.f;

    produce_tile(smem + SM_STAGES, xb, W1, W2, gw.x, gw.y, 0, tid);
    __syncthreads();

    const int arow0 = warp_m * 64 + (lane & 15);
    const int ahalf = lane >> 4;           // 0..1
    const int brow0 = warp_n * 32 + (lane & 7);
    const int bhalf = (lane >> 3) & 1;     // 0..1

    for (int t = 0; t < NKT; t++) {
        char* cbuf = smem + SM_STAGES + (t & 1) * STAGE_BYTES;
        const uint32_t aHiB = smem_u32(cbuf + OFF_A_HI);
        const uint32_t aLoB = smem_u32(cbuf + OFF_A_LO);
        const uint32_t bHiB = smem_u32(cbuf + OFF_B_HI);
        const uint32_t bLoB = smem_u32(cbuf + OFF_B_LO);

#pragma unroll
        for (int s = 0; s < 2; s++) {      // 2 k16 steps per 32-wide tile
            const int aq = 2 * s + ahalf;
            const int bq = 2 * s + bhalf;
            uint32_t aX[4][4];

            // ---- pass A-hi: hi*hi + hi*lo ----
#pragma unroll
            for (int mi = 0; mi < 4; mi++)
                LDSM4(aX[mi], aHiB + swoff(arow0 + mi * 16, aq));
#pragma unroll
            for (int nj = 0; nj < 4; nj++) {
                uint32_t bh[2], bl[2];
                uint32_t boff = swoff(brow0 + nj * 8, bq);
                LDSM2(bh, bHiB + boff);
                LDSM2(bl, bLoB + boff);
#pragma unroll
                for (int mi = 0; mi < 4; mi++) {
                    MMA16816(acc[mi][nj], aX[mi], bh);
                    MMA16816(acc[mi][nj], aX[mi], bl);
                }
            }
            // ---- pass A-lo: lo*hi ----
#pragma unroll
            for (int mi = 0; mi < 4; mi++)
                LDSM4(aX[mi], aLoB + swoff(arow0 + mi * 16, aq));
#pragma unroll
            for (int nj = 0; nj < 4; nj++) {
                uint32_t bh[2];
                LDSM2(bh, bHiB + swoff(brow0 + nj * 8, bq));
#pragma unroll
                for (int mi = 0; mi < 4; mi++)
                    MMA16816(acc[mi][nj], aX[mi], bh);
            }
        }

        if (t + 1 < NKT)
            produce_tile(smem + SM_STAGES + ((t + 1) & 1) * STAGE_BYTES,
                         xb, W1, W2, gw.x, gw.y, (t + 1) * BK, tid);
        __syncthreads();
    }

    // ---- epilogue: bias add, bf16 rounding, direct fp32 store ----
    const int r_base = warp_m * 64 + (lane >> 2);
    const int c_base = warp_n * 32 + ((lane & 3) << 1);
#pragma unroll
    for (int mi = 0; mi < 4; mi++) {
#pragma unroll
        for (int half = 0; half < 2; half++) {
            int l = r_base + mi * 16 + half * 8;
            if (l >= L_) continue;
            float* orow = out + ((size_t)b * L_ + l) * D_ + dtile * BN;
#pragma unroll
            for (int nj = 0; nj < 4; nj++) {
                int c = c_base + nj * 8;
                float v0 = acc[mi][nj][half * 2 + 0] + bm[c];
                float v1 = acc[mi][nj][half * 2 + 1] + bm[c + 1];
                v0 = __bfloat162float(__float2bfloat16_rn(v0));
                v1 = __bfloat162float(__float2bfloat16_rn(v1));
                *(float2*)(orow + c) = make_float2(v0, v1);
            }
        }
    }
}

// ---------------------------------------------------------------------------
extern "C" void kernel_launch(void* const* d_in, const int* in_sizes, int n_in,
                              void* d_out, int out_size) {
    const void* x_p = nullptr;
    const void* W_p = nullptr;
    const void* b_p = nullptr;
    const void* c1024[2] = {nullptr, nullptr};
    int n1024 = 0;

    for (int i = 0; i < n_in; i++) {
        switch (in_sizes[i]) {
            case 11520000: x_p = d_in[i]; break;
            case 3686400:  W_p = d_in[i]; break;
            case 4096:     b_p = d_in[i]; break;
            case 1024: if (n1024 < 2) c1024[n1024++] = d_in[i]; break;
            default: break;
        }
    }
    if (!x_p || !W_p || !b_p || n1024 != 2) {
        x_p = d_in[0]; c1024[0] = d_in[1]; c1024[1] = d_in[2];
        W_p = d_in[3]; b_p = d_in[4];
    }

    float* out = (float*)d_out;

    cudaFuncSetAttribute(moe_hmma_kernel,
                         cudaFuncAttributeMaxDynamicSharedMemorySize, SMEM_TOTAL);

    gates_kernel<<<1, B_>>>(c1024[0], c1024[1]);

    dim3 grid(D_ / BN, B_);   // (4, 128)
    moe_hmma_kernel<<<grid, 256, SMEM_TOTAL>>>((const float*)x_p, (const float*)W_p,
                                               (const float*)b_p, out);
}